// round 11
// baseline (speedup 1.0000x reference)
#include <cuda_runtime.h>
#include <cuda_bf16.h>
#include <cuda_fp16.h>
#include <cstdint>
#include <math.h>

// ---------------------------------------------------------------------------
// Shapes fixed by the dataset
#define D_DIM   256
#define E_DIM   256
#define K_NEIGH 32
#define N_NODES 200000
#define B_PAD   50048          // 391 * 128  (GEMM M-tile padded)

// Scratch (__device__ globals: no allocations allowed)
__device__ __nv_bfloat16 g_Xh[(size_t)B_PAD * 512];   // activation hi plane
__device__ __nv_bfloat16 g_Xl[(size_t)B_PAD * 512];   // activation lo plane
__device__ __nv_bfloat16 g_Wth[256 * 512];            // W^T hi  [e][k]
__device__ __nv_bfloat16 g_Wtl[256 * 512];            // W^T lo  [e][k]
__device__ float         g_bc[256];                   // fused bias
__device__ __half        g_F16[(size_t)N_NODES * 256]; // fp16 feature table (neigh path)

// ---------------------------------------------------------------------------
// Setup kernel: merged feature fp32->fp16 convert + fused-weight prep.
// Convert: 4 float4 per thread -> 12500 blocks; prep: 513 blocks after.
// ---------------------------------------------------------------------------
#define CONV_BLOCKS 12500      // 200000*256/4 float4 / (256 thr * 4 each)

static __device__ __forceinline__ void split_wt(float s, int e, int d) {
    __nv_bfloat16 h = __float2bfloat16_rn(s);
    float r = s - __bfloat162float(h);
    g_Wth[e * 512 + d] = h;
    g_Wtl[e * 512 + d] = __float2bfloat16_rn(r);
}

__global__ void __launch_bounds__(256) setup_kernel(const float* __restrict__ features,
                                                    const float* __restrict__ W_init,
                                                    const float* __restrict__ b_init,
                                                    const float* __restrict__ W_final,
                                                    const float* __restrict__ b_final) {
    if (blockIdx.x < CONV_BLOCKS) {
        // 4 consecutive float4 per thread (64B read, 32B write)
        const size_t base = ((size_t)blockIdx.x * 256 + threadIdx.x) * 4;
#pragma unroll
        for (int j = 0; j < 4; j++) {
            const size_t i = base + j;
            float4 v = __ldcs(((const float4*)features) + i);   // read-once: don't pollute L2
            __half2 p0 = __floats2half2_rn(v.x, v.y);
            __half2 p1 = __floats2half2_rn(v.z, v.w);
            uint2 u;
            u.x = *(uint32_t*)&p0;
            u.y = *(uint32_t*)&p1;
            *(uint2*)(g_F16 + i * 4) = u;    // default store: keep table in L2
        }
        return;
    }

    __shared__ float sh[256];
    const int d = blockIdx.x - CONV_BLOCKS;
    const int e = threadIdx.x;

    if (d < 256) {
        sh[e] = W_init[d * 256 + e];
        __syncthreads();
        float s0 = 0.f, s1 = 0.f, s2 = 0.f, s3 = 0.f;
#pragma unroll 8
        for (int j = 0; j < 256; j += 4) {
            s0 += sh[j + 0] * W_final[(j + 0) * 256 + e];
            s1 += sh[j + 1] * W_final[(j + 1) * 256 + e];
            s2 += sh[j + 2] * W_final[(j + 2) * 256 + e];
            s3 += sh[j + 3] * W_final[(j + 3) * 256 + e];
        }
        split_wt((s0 + s1) + (s2 + s3), e, d);
    } else if (d < 512) {
        split_wt(W_final[d * 256 + e], e, d);
    } else {
        sh[e] = b_init[e];
        __syncthreads();
        float s0 = 0.f, s1 = 0.f, s2 = 0.f, s3 = 0.f;
#pragma unroll 8
        for (int j = 0; j < 256; j += 4) {
            s0 += sh[j + 0] * W_final[(j + 0) * 256 + e];
            s1 += sh[j + 1] * W_final[(j + 1) * 256 + e];
            s2 += sh[j + 2] * W_final[(j + 2) * 256 + e];
            s3 += sh[j + 3] * W_final[(j + 3) * 256 + e];
        }
        g_bc[e] = b_final[e] + (s0 + s1) + (s2 + s3);
    }
}

// ---------------------------------------------------------------------------
// Kernel 1: gather + weighted-mean aggregate -> X hi/lo bf16 planes
// Self path: exact fp32 rows via __ldcs (read-once, keep L2 for fp16 table).
// X writes via __stcs (evict-first) for the same reason.
// ---------------------------------------------------------------------------
static __device__ __forceinline__ void split_store4_cs(float4 v, __nv_bfloat16* hp, __nv_bfloat16* lp) {
    __nv_bfloat16 h0 = __float2bfloat16_rn(v.x), h1 = __float2bfloat16_rn(v.y),
                  h2 = __float2bfloat16_rn(v.z), h3 = __float2bfloat16_rn(v.w);
    float r0 = v.x - __bfloat162float(h0), r1 = v.y - __bfloat162float(h1),
          r2 = v.z - __bfloat162float(h2), r3 = v.w - __bfloat162float(h3);
    __nv_bfloat162 H0; H0.x = h0; H0.y = h1;
    __nv_bfloat162 H1; H1.x = h2; H1.y = h3;
    __nv_bfloat162 L0; L0.x = __float2bfloat16_rn(r0); L0.y = __float2bfloat16_rn(r1);
    __nv_bfloat162 L1; L1.x = __float2bfloat16_rn(r2); L1.y = __float2bfloat16_rn(r3);
    uint2 hu, lu;
    hu.x = *(uint32_t*)&H0; hu.y = *(uint32_t*)&H1;
    lu.x = *(uint32_t*)&L0; lu.y = *(uint32_t*)&L1;
    __stcs((uint2*)hp, hu);
    __stcs((uint2*)lp, lu);
}

__global__ void __launch_bounds__(256) gather_kernel(const int*   __restrict__ nodes,
                                                     const int*   __restrict__ neigh_idx,
                                                     const float* __restrict__ neigh_w,
                                                     const float* __restrict__ features,
                                                     int B) {
    const int wid  = threadIdx.x >> 5;
    const int lane = threadIdx.x & 31;
    const int b    = blockIdx.x * 8 + wid;
    if (b >= B_PAD) return;

    __nv_bfloat16* xh = g_Xh + (size_t)b * 512;
    __nv_bfloat16* xl = g_Xl + (size_t)b * 512;

    float4 s0, s1, a0, a1;
    if (b < B) {
        const int node = nodes[b];
        const float4* fs = (const float4*)(features + (size_t)node * D_DIM);
        s0 = __ldcs(fs + lane);         // read-once: evict-first
        s1 = __ldcs(fs + lane + 32);

        const float w_mine   = neigh_w[b * K_NEIGH + lane];
        const int   idx_mine = neigh_idx[b * K_NEIGH + lane];
        float ws = w_mine;
#pragma unroll
        for (int o = 16; o > 0; o >>= 1)
            ws += __shfl_xor_sync(0xffffffffu, ws, o);
        const float inv = 1.0f / ws;

        a0 = make_float4(0.f, 0.f, 0.f, 0.f);
        a1 = make_float4(0.f, 0.f, 0.f, 0.f);
#pragma unroll 8
        for (int k = 0; k < K_NEIGH; k++) {
            const float wk = __shfl_sync(0xffffffffu, w_mine, k) * inv;
            const int   ik = __shfl_sync(0xffffffffu, idx_mine, k);
            uint4 v = *(const uint4*)(g_F16 + (size_t)ik * 256 + lane * 8);  // default: L2-cache
            float2 f0 = __half22float2(*(__half2*)&v.x);
            float2 f1 = __half22float2(*(__half2*)&v.y);
            float2 f2 = __half22float2(*(__half2*)&v.z);
            float2 f3 = __half22float2(*(__half2*)&v.w);
            a0.x += wk * f0.x; a0.y += wk * f0.y; a0.z += wk * f1.x; a0.w += wk * f1.y;
            a1.x += wk * f2.x; a1.y += wk * f2.y; a1.z += wk * f3.x; a1.w += wk * f3.y;
        }
    } else {
        s0 = s1 = a0 = a1 = make_float4(0.f, 0.f, 0.f, 0.f);
    }

    split_store4_cs(s0, xh + lane * 4,       xl + lane * 4);
    split_store4_cs(s1, xh + 128 + lane * 4, xl + 128 + lane * 4);
    split_store4_cs(a0, xh + 256 + lane * 8,     xl + 256 + lane * 8);
    split_store4_cs(a1, xh + 256 + lane * 8 + 4, xl + 256 + lane * 8 + 4);
}

// ---------------------------------------------------------------------------
// Kernel 2 (R9 proven config): tensor-core GEMM via mma.sync, cp.async
// double-buffered. CTA tile 128M x 128N, 8 warps (4M x 2N), warp tile 32x64.
// KC=32 per stage, 16 stages, 2 smem buffers (40KB each), 2 CTAs/SM.
// ---------------------------------------------------------------------------
#define KC       32
#define KSTRIDE  40                  // padded row stride (bf16 elems) — conflict-free
#define PLANE_E  (128 * KSTRIDE)     // 5120 elems per plane
#define STAGE_E  (4 * PLANE_E)       // 20480 elems per stage
#define STAGE_B  (STAGE_E * 2)       // 40960 bytes
#define SMEM_B   (2 * STAGE_B)       // 81920 bytes

static __device__ __forceinline__ uint32_t smem_u32(const void* p) {
    uint32_t a;
    asm("{ .reg .u64 t; cvta.to.shared.u64 t, %1; cvt.u32.u64 %0, t; }" : "=r"(a) : "l"(p));
    return a;
}
static __device__ __forceinline__ void cp16(uint32_t saddr, const void* g) {
    asm volatile("cp.async.cg.shared.global [%0], [%1], 16;"
                 :: "r"(saddr), "l"((size_t)__cvta_generic_to_global(g)));
}
#define CP_COMMIT() asm volatile("cp.async.commit_group;" ::: "memory")
#define CP_WAIT(n)  asm volatile("cp.async.wait_group %0;" :: "n"(n) : "memory")

static __device__ __forceinline__ void mma16816(float* c, const uint32_t* a, const uint32_t* b) {
    asm volatile(
        "mma.sync.aligned.m16n8k16.row.col.f32.bf16.bf16.f32 "
        "{%0,%1,%2,%3}, {%4,%5,%6,%7}, {%8,%9}, {%0,%1,%2,%3};"
        : "+f"(c[0]), "+f"(c[1]), "+f"(c[2]), "+f"(c[3])
        : "r"(a[0]), "r"(a[1]), "r"(a[2]), "r"(a[3]), "r"(b[0]), "r"(b[1]));
}

__global__ void __launch_bounds__(256, 2) gemm_kernel(float* __restrict__ out, int B) {
    extern __shared__ __nv_bfloat16 smem[];
    const uint32_t sbase = smem_u32(smem);

    const int tid  = threadIdx.x;
    const int wid  = tid >> 5;
    const int lane = tid & 31;
    const int b0   = (blockIdx.x >> 1) * 128;
    const int n0   = (blockIdx.x & 1) * 128;

    const int wm = (wid & 3) * 32;    // warp M offset
    const int wn = (wid >> 2) * 64;   // warp N offset
    const int qr = lane >> 2;         // 0..7
    const int qc = lane & 3;          // 0..3

    const int i0   = tid;             // 0..255
    const int i1   = tid + 256;       // 256..511
    const int row0 = i0 >> 2, seg0 = i0 & 3;
    const int row1 = i1 >> 2, seg1 = i1 & 3;

    float acc[2][8][4];
#pragma unroll
    for (int mi = 0; mi < 2; mi++)
#pragma unroll
        for (int ni = 0; ni < 8; ni++)
#pragma unroll
            for (int j = 0; j < 4; j++)
                acc[mi][ni][j] = 0.f;

    auto prefetch = [&](int buf, int kc) {
        const uint32_t sb = sbase + (uint32_t)buf * STAGE_B;
        {
            const size_t goA = (size_t)(b0 + row0) * 512 + kc + seg0 * 8;
            const size_t goW = (size_t)(n0 + row0) * 512 + kc + seg0 * 8;
            const uint32_t so = (uint32_t)(row0 * KSTRIDE + seg0 * 8) * 2;
            cp16(sb + so,                  g_Xh  + goA);
            cp16(sb + PLANE_E * 2 + so,    g_Xl  + goA);
            cp16(sb + PLANE_E * 4 + so,    g_Wth + goW);
            cp16(sb + PLANE_E * 6 + so,    g_Wtl + goW);
        }
        {
            const size_t goA = (size_t)(b0 + row1) * 512 + kc + seg1 * 8;
            const size_t goW = (size_t)(n0 + row1) * 512 + kc + seg1 * 8;
            const uint32_t so = (uint32_t)(row1 * KSTRIDE + seg1 * 8) * 2;
            cp16(sb + so,                  g_Xh  + goA);
            cp16(sb + PLANE_E * 2 + so,    g_Xl  + goA);
            cp16(sb + PLANE_E * 4 + so,    g_Wth + goW);
            cp16(sb + PLANE_E * 6 + so,    g_Wtl + goW);
        }
    };

    prefetch(0, 0);
    CP_COMMIT();

    for (int chunk = 0; chunk < 16; chunk++) {
        if (chunk + 1 < 16) {
            prefetch((chunk + 1) & 1, (chunk + 1) * KC);
            CP_COMMIT();
            CP_WAIT(1);          // current buffer's loads complete
        } else {
            CP_WAIT(0);
        }
        __syncthreads();

        const __nv_bfloat16* st  = smem + (chunk & 1) * STAGE_E;
        const __nv_bfloat16* sAh = st;
        const __nv_bfloat16* sAl = st + PLANE_E;
        const __nv_bfloat16* sWh = st + 2 * PLANE_E;
        const __nv_bfloat16* sWl = st + 3 * PLANE_E;

#pragma unroll
        for (int kk = 0; kk < KC; kk += 16) {
            uint32_t ah[2][4], al[2][4];
#pragma unroll
            for (int mi = 0; mi < 2; mi++) {
                const int r0 = wm + mi * 16 + qr;
                const int c0 = kk + qc * 2;
                ah[mi][0] = *(const uint32_t*)(sAh + (r0)     * KSTRIDE + c0);
                ah[mi][1] = *(const uint32_t*)(sAh + (r0 + 8) * KSTRIDE + c0);
                ah[mi][2] = *(const uint32_t*)(sAh + (r0)     * KSTRIDE + c0 + 8);
                ah[mi][3] = *(const uint32_t*)(sAh + (r0 + 8) * KSTRIDE + c0 + 8);
                al[mi][0] = *(const uint32_t*)(sAl + (r0)     * KSTRIDE + c0);
                al[mi][1] = *(const uint32_t*)(sAl + (r0 + 8) * KSTRIDE + c0);
                al[mi][2] = *(const uint32_t*)(sAl + (r0)     * KSTRIDE + c0 + 8);
                al[mi][3] = *(const uint32_t*)(sAl + (r0 + 8) * KSTRIDE + c0 + 8);
            }
#pragma unroll
            for (int ni = 0; ni < 8; ni++) {
                const int n  = wn + ni * 8 + qr;
                const int k0 = kk + qc * 2;
                uint32_t bh[2], bl[2];
                bh[0] = *(const uint32_t*)(sWh + n * KSTRIDE + k0);
                bh[1] = *(const uint32_t*)(sWh + n * KSTRIDE + k0 + 8);
                bl[0] = *(const uint32_t*)(sWl + n * KSTRIDE + k0);
                bl[1] = *(const uint32_t*)(sWl + n * KSTRIDE + k0 + 8);
#pragma unroll
                for (int mi = 0; mi < 2; mi++) {
                    mma16816(acc[mi][ni], ah[mi], bh);
                    mma16816(acc[mi][ni], al[mi], bh);
                    mma16816(acc[mi][ni], ah[mi], bl);
                }
            }
        }
        __syncthreads();   // buffer consumed; next iteration may overwrite it
    }

    // ---- epilogue: bias + swish + store ----
#pragma unroll
    for (int mi = 0; mi < 2; mi++) {
        const int row = b0 + wm + mi * 16 + qr;
#pragma unroll
        for (int ni = 0; ni < 8; ni++) {
            const int col = n0 + wn + ni * 8 + qc * 2;
            const float b_0 = g_bc[col], b_1 = g_bc[col + 1];

            if (row < B) {
                float z0 = acc[mi][ni][0] + b_0;
                float z1 = acc[mi][ni][1] + b_1;
                float2 o;
                o.x = z0 / (1.f + expf(-z0));
                o.y = z1 / (1.f + expf(-z1));
                *(float2*)(out + (size_t)row * E_DIM + col) = o;
            }
            if (row + 8 < B) {
                float z2 = acc[mi][ni][2] + b_0;
                float z3 = acc[mi][ni][3] + b_1;
                float2 o;
                o.x = z2 / (1.f + expf(-z2));
                o.y = z3 / (1.f + expf(-z3));
                *(float2*)(out + (size_t)(row + 8) * E_DIM + col) = o;
            }
        }
    }
}

// ---------------------------------------------------------------------------
extern "C" void kernel_launch(void* const* d_in, const int* in_sizes, int n_in,
                              void* d_out, int out_size) {
    const int*   nodes     = (const int*)  d_in[0];
    const int*   neigh_idx = (const int*)  d_in[1];
    const float* neigh_w   = (const float*)d_in[2];
    const float* features  = (const float*)d_in[3];
    const float* W_init    = (const float*)d_in[4];
    const float* b_init    = (const float*)d_in[5];
    const float* W_final   = (const float*)d_in[6];
    const float* b_final   = (const float*)d_in[7];
    float*       out       = (float*)d_out;

    const int B = in_sizes[0];

    static bool attr_set = false;
    if (!attr_set) {
        cudaFuncSetAttribute(gemm_kernel, cudaFuncAttributeMaxDynamicSharedMemorySize, SMEM_B);
        attr_set = true;
    }

    setup_kernel<<<CONV_BLOCKS + 513, 256>>>(features, W_init, b_init, W_final, b_final);
    gather_kernel<<<B_PAD / 8, 256>>>(nodes, neigh_idx, neigh_w, features, B);
    gemm_kernel<<<(B_PAD / 128) * 2, 256, SMEM_B>>>(out, B);
}

// round 12
// speedup vs baseline: 1.3181x; 1.3181x over previous
#include <cuda_runtime.h>
#include <cuda_fp16.h>
#include <cstdint>
#include <math.h>

// ---------------------------------------------------------------------------
// Shapes fixed by the dataset
#define D_DIM   256
#define E_DIM   256
#define K_NEIGH 32
#define N_NODES 200000
#define B_PAD   50048          // 391 * 128  (GEMM M-tile padded)

// Scratch (__device__ globals: no allocations allowed)
__device__ __half g_Xh[(size_t)B_PAD * 512];    // activation hi plane (fp16)
__device__ __half g_Xl[(size_t)B_PAD * 512];    // activation lo plane (fp16 residual)
__device__ __half g_Wt[256 * 512];              // W^T single plane (fp16) [e][k]
__device__ float  g_bc[256];                    // fused bias
__device__ __half g_F16[(size_t)N_NODES * 256]; // fp16 feature table (neigh path)

// ---------------------------------------------------------------------------
// Setup kernel (R9-proven convert shape): merged fp32->fp16 feature convert
// + fused-weight prep. blocks [0,50000): convert; [50000,50513): prep.
// ---------------------------------------------------------------------------
#define CONV_BLOCKS 50000      // 200000*256/4 float4 / 256 thr

__global__ void __launch_bounds__(256) setup_kernel(const float* __restrict__ features,
                                                    const float* __restrict__ W_init,
                                                    const float* __restrict__ b_init,
                                                    const float* __restrict__ W_final,
                                                    const float* __restrict__ b_final) {
    if (blockIdx.x < CONV_BLOCKS) {
        const size_t i = (size_t)blockIdx.x * 256 + threadIdx.x;   // one float4 each
        float4 v = ((const float4*)features)[i];
        __half2 p0 = __floats2half2_rn(v.x, v.y);
        __half2 p1 = __floats2half2_rn(v.z, v.w);
        uint2 u;
        u.x = *(uint32_t*)&p0;
        u.y = *(uint32_t*)&p1;
        *(uint2*)(g_F16 + i * 4) = u;
        return;
    }

    __shared__ float sh[256];
    const int d = blockIdx.x - CONV_BLOCKS;
    const int e = threadIdx.x;

    if (d < 256) {
        sh[e] = W_init[d * 256 + e];
        __syncthreads();
        float s0 = 0.f, s1 = 0.f, s2 = 0.f, s3 = 0.f;
#pragma unroll 8
        for (int j = 0; j < 256; j += 4) {
            s0 += sh[j + 0] * W_final[(j + 0) * 256 + e];
            s1 += sh[j + 1] * W_final[(j + 1) * 256 + e];
            s2 += sh[j + 2] * W_final[(j + 2) * 256 + e];
            s3 += sh[j + 3] * W_final[(j + 3) * 256 + e];
        }
        g_Wt[e * 512 + d] = __float2half_rn((s0 + s1) + (s2 + s3));
    } else if (d < 512) {
        g_Wt[e * 512 + d] = __float2half_rn(W_final[d * 256 + e]);
    } else {
        sh[e] = b_init[e];
        __syncthreads();
        float s0 = 0.f, s1 = 0.f, s2 = 0.f, s3 = 0.f;
#pragma unroll 8
        for (int j = 0; j < 256; j += 4) {
            s0 += sh[j + 0] * W_final[(j + 0) * 256 + e];
            s1 += sh[j + 1] * W_final[(j + 1) * 256 + e];
            s2 += sh[j + 2] * W_final[(j + 2) * 256 + e];
            s3 += sh[j + 3] * W_final[(j + 3) * 256 + e];
        }
        g_bc[e] = b_final[e] + (s0 + s1) + (s2 + s3);
    }
}

// ---------------------------------------------------------------------------
// Kernel 1: gather + weighted-mean aggregate -> X hi/lo fp16 planes.
// Self path: exact fp32 rows; neighbor path: fp16 table. Plain loads/stores
// (R11's cache hints regressed; reverted).
// ---------------------------------------------------------------------------
static __device__ __forceinline__ void split_store4(float4 v, __half* hp, __half* lp) {
    __half h0 = __float2half_rn(v.x), h1 = __float2half_rn(v.y),
           h2 = __float2half_rn(v.z), h3 = __float2half_rn(v.w);
    float r0 = v.x - __half2float(h0), r1 = v.y - __half2float(h1),
          r2 = v.z - __half2float(h2), r3 = v.w - __half2float(h3);
    __half2 H0 = __halves2half2(h0, h1), H1 = __halves2half2(h2, h3);
    __half2 L0 = __floats2half2_rn(r0, r1), L1 = __floats2half2_rn(r2, r3);
    uint2 hu, lu;
    hu.x = *(uint32_t*)&H0; hu.y = *(uint32_t*)&H1;
    lu.x = *(uint32_t*)&L0; lu.y = *(uint32_t*)&L1;
    *(uint2*)hp = hu;
    *(uint2*)lp = lu;
}

__global__ void __launch_bounds__(256) gather_kernel(const int*   __restrict__ nodes,
                                                     const int*   __restrict__ neigh_idx,
                                                     const float* __restrict__ neigh_w,
                                                     const float* __restrict__ features,
                                                     int B) {
    const int wid  = threadIdx.x >> 5;
    const int lane = threadIdx.x & 31;
    const int b    = blockIdx.x * 8 + wid;
    if (b >= B_PAD) return;

    __half* xh = g_Xh + (size_t)b * 512;
    __half* xl = g_Xl + (size_t)b * 512;

    float4 s0, s1, a0, a1;
    if (b < B) {
        const int node = nodes[b];
        const float4* fs = (const float4*)(features + (size_t)node * D_DIM);
        s0 = fs[lane];
        s1 = fs[lane + 32];

        const float w_mine   = neigh_w[b * K_NEIGH + lane];
        const int   idx_mine = neigh_idx[b * K_NEIGH + lane];
        float ws = w_mine;
#pragma unroll
        for (int o = 16; o > 0; o >>= 1)
            ws += __shfl_xor_sync(0xffffffffu, ws, o);
        const float inv = 1.0f / ws;

        a0 = make_float4(0.f, 0.f, 0.f, 0.f);
        a1 = make_float4(0.f, 0.f, 0.f, 0.f);
#pragma unroll 8
        for (int k = 0; k < K_NEIGH; k++) {
            const float wk = __shfl_sync(0xffffffffu, w_mine, k) * inv;
            const int   ik = __shfl_sync(0xffffffffu, idx_mine, k);
            uint4 v = *(const uint4*)(g_F16 + (size_t)ik * 256 + lane * 8);
            float2 f0 = __half22float2(*(__half2*)&v.x);
            float2 f1 = __half22float2(*(__half2*)&v.y);
            float2 f2 = __half22float2(*(__half2*)&v.z);
            float2 f3 = __half22float2(*(__half2*)&v.w);
            a0.x += wk * f0.x; a0.y += wk * f0.y; a0.z += wk * f1.x; a0.w += wk * f1.y;
            a1.x += wk * f2.x; a1.y += wk * f2.y; a1.z += wk * f3.x; a1.w += wk * f3.y;
        }
    } else {
        s0 = s1 = a0 = a1 = make_float4(0.f, 0.f, 0.f, 0.f);
    }

    split_store4(s0, xh + lane * 4,       xl + lane * 4);
    split_store4(s1, xh + 128 + lane * 4, xl + 128 + lane * 4);
    split_store4(a0, xh + 256 + lane * 8,     xl + 256 + lane * 8);
    split_store4(a1, xh + 256 + lane * 8 + 4, xl + 256 + lane * 8 + 4);
}

// ---------------------------------------------------------------------------
// Kernel 2: tensor-core GEMM via mma.sync (f16 x f16 -> f32), cp.async
// double-buffered. z = (Ah + Al) * W, 2 MMA products per fragment.
// CTA tile 128M x 128N, 8 warps (4M x 2N), warp tile 32x64.
// KC=32 per stage, 16 stages, 2 smem buffers (30KB each), 2 CTAs/SM.
// ---------------------------------------------------------------------------
#define KC       32
#define KSTRIDE  40                  // padded row stride (fp16 elems) — conflict-free
#define PLANE_E  (128 * KSTRIDE)     // 5120 elems per plane
#define STAGE_E  (3 * PLANE_E)       // 15360 elems per stage (Ah, Al, W)
#define STAGE_B  (STAGE_E * 2)       // 30720 bytes
#define SMEM_B   (2 * STAGE_B)       // 61440 bytes

#define OFF_AH   0
#define OFF_AL   PLANE_E
#define OFF_W    (2 * PLANE_E)

static __device__ __forceinline__ uint32_t smem_u32(const void* p) {
    uint32_t a;
    asm("{ .reg .u64 t; cvta.to.shared.u64 t, %1; cvt.u32.u64 %0, t; }" : "=r"(a) : "l"(p));
    return a;
}
static __device__ __forceinline__ void cp16(uint32_t saddr, const void* g) {
    asm volatile("cp.async.cg.shared.global [%0], [%1], 16;"
                 :: "r"(saddr), "l"((size_t)__cvta_generic_to_global(g)));
}
#define CP_COMMIT() asm volatile("cp.async.commit_group;" ::: "memory")
#define CP_WAIT(n)  asm volatile("cp.async.wait_group %0;" :: "n"(n) : "memory")

static __device__ __forceinline__ void mma16816(float* c, const uint32_t* a, const uint32_t* b) {
    asm volatile(
        "mma.sync.aligned.m16n8k16.row.col.f32.f16.f16.f32 "
        "{%0,%1,%2,%3}, {%4,%5,%6,%7}, {%8,%9}, {%0,%1,%2,%3};"
        : "+f"(c[0]), "+f"(c[1]), "+f"(c[2]), "+f"(c[3])
        : "r"(a[0]), "r"(a[1]), "r"(a[2]), "r"(a[3]), "r"(b[0]), "r"(b[1]));
}

__global__ void __launch_bounds__(256, 2) gemm_kernel(float* __restrict__ out, int B) {
    extern __shared__ __half smem[];
    const uint32_t sbase = smem_u32(smem);

    const int tid  = threadIdx.x;
    const int wid  = tid >> 5;
    const int lane = tid & 31;
    const int b0   = (blockIdx.x >> 1) * 128;
    const int n0   = (blockIdx.x & 1) * 128;

    const int wm = (wid & 3) * 32;    // warp M offset
    const int wn = (wid >> 2) * 64;   // warp N offset
    const int qr = lane >> 2;         // 0..7
    const int qc = lane & 3;          // 0..3

    const int row0 = tid >> 2,          seg0 = tid & 3;          // rows 0..63
    const int row1 = (tid + 256) >> 2,  seg1 = tid & 3;          // rows 64..127

    float acc[2][8][4];
#pragma unroll
    for (int mi = 0; mi < 2; mi++)
#pragma unroll
        for (int ni = 0; ni < 8; ni++)
#pragma unroll
            for (int j = 0; j < 4; j++)
                acc[mi][ni][j] = 0.f;

    auto prefetch = [&](int buf, int kc) {
        const uint32_t sb = sbase + (uint32_t)buf * STAGE_B;
        {
            const size_t goA = (size_t)(b0 + row0) * 512 + kc + seg0 * 8;
            const size_t goW = (size_t)(n0 + row0) * 512 + kc + seg0 * 8;
            const uint32_t so = (uint32_t)(row0 * KSTRIDE + seg0 * 8) * 2;
            cp16(sb + OFF_AH * 2 + so, g_Xh + goA);
            cp16(sb + OFF_AL * 2 + so, g_Xl + goA);
            cp16(sb + OFF_W  * 2 + so, g_Wt + goW);
        }
        {
            const size_t goA = (size_t)(b0 + row1) * 512 + kc + seg1 * 8;
            const size_t goW = (size_t)(n0 + row1) * 512 + kc + seg1 * 8;
            const uint32_t so = (uint32_t)(row1 * KSTRIDE + seg1 * 8) * 2;
            cp16(sb + OFF_AH * 2 + so, g_Xh + goA);
            cp16(sb + OFF_AL * 2 + so, g_Xl + goA);
            cp16(sb + OFF_W  * 2 + so, g_Wt + goW);
        }
    };

    prefetch(0, 0);
    CP_COMMIT();

    for (int chunk = 0; chunk < 16; chunk++) {
        if (chunk + 1 < 16) {
            prefetch((chunk + 1) & 1, (chunk + 1) * KC);
            CP_COMMIT();
            CP_WAIT(1);          // current buffer's loads complete
        } else {
            CP_WAIT(0);
        }
        __syncthreads();

        const __half* st  = smem + (chunk & 1) * STAGE_E;
        const __half* sAh = st + OFF_AH;
        const __half* sAl = st + OFF_AL;
        const __half* sW  = st + OFF_W;

#pragma unroll
        for (int kk = 0; kk < KC; kk += 16) {
            uint32_t ah[2][4], al[2][4];
#pragma unroll
            for (int mi = 0; mi < 2; mi++) {
                const int r0 = wm + mi * 16 + qr;
                const int c0 = kk + qc * 2;
                ah[mi][0] = *(const uint32_t*)(sAh + (r0)     * KSTRIDE + c0);
                ah[mi][1] = *(const uint32_t*)(sAh + (r0 + 8) * KSTRIDE + c0);
                ah[mi][2] = *(const uint32_t*)(sAh + (r0)     * KSTRIDE + c0 + 8);
                ah[mi][3] = *(const uint32_t*)(sAh + (r0 + 8) * KSTRIDE + c0 + 8);
                al[mi][0] = *(const uint32_t*)(sAl + (r0)     * KSTRIDE + c0);
                al[mi][1] = *(const uint32_t*)(sAl + (r0 + 8) * KSTRIDE + c0);
                al[mi][2] = *(const uint32_t*)(sAl + (r0)     * KSTRIDE + c0 + 8);
                al[mi][3] = *(const uint32_t*)(sAl + (r0 + 8) * KSTRIDE + c0 + 8);
            }
#pragma unroll
            for (int ni = 0; ni < 8; ni++) {
                const int n  = wn + ni * 8 + qr;
                const int k0 = kk + qc * 2;
                uint32_t bw[2];
                bw[0] = *(const uint32_t*)(sW + n * KSTRIDE + k0);
                bw[1] = *(const uint32_t*)(sW + n * KSTRIDE + k0 + 8);
#pragma unroll
                for (int mi = 0; mi < 2; mi++) {
                    mma16816(acc[mi][ni], ah[mi], bw);
                    mma16816(acc[mi][ni], al[mi], bw);
                }
            }
        }
        __syncthreads();   // buffer consumed; next iteration may overwrite it
    }

    // ---- epilogue: bias + swish + store ----
#pragma unroll
    for (int mi = 0; mi < 2; mi++) {
        const int row = b0 + wm + mi * 16 + qr;
#pragma unroll
        for (int ni = 0; ni < 8; ni++) {
            const int col = n0 + wn + ni * 8 + qc * 2;
            const float b_0 = g_bc[col], b_1 = g_bc[col + 1];

            if (row < B) {
                float z0 = acc[mi][ni][0] + b_0;
                float z1 = acc[mi][ni][1] + b_1;
                float2 o;
                o.x = z0 / (1.f + expf(-z0));
                o.y = z1 / (1.f + expf(-z1));
                *(float2*)(out + (size_t)row * E_DIM + col) = o;
            }
            if (row + 8 < B) {
                float z2 = acc[mi][ni][2] + b_0;
                float z3 = acc[mi][ni][3] + b_1;
                float2 o;
                o.x = z2 / (1.f + expf(-z2));
                o.y = z3 / (1.f + expf(-z3));
                *(float2*)(out + (size_t)(row + 8) * E_DIM + col) = o;
            }
        }
    }
}

// ---------------------------------------------------------------------------
extern "C" void kernel_launch(void* const* d_in, const int* in_sizes, int n_in,
                              void* d_out, int out_size) {
    const int*   nodes     = (const int*)  d_in[0];
    const int*   neigh_idx = (const int*)  d_in[1];
    const float* neigh_w   = (const float*)d_in[2];
    const float* features  = (const float*)d_in[3];
    const float* W_init    = (const float*)d_in[4];
    const float* b_init    = (const float*)d_in[5];
    const float* W_final   = (const float*)d_in[6];
    const float* b_final   = (const float*)d_in[7];
    float*       out       = (float*)d_out;

    const int B = in_sizes[0];

    static bool attr_set = false;
    if (!attr_set) {
        cudaFuncSetAttribute(gemm_kernel, cudaFuncAttributeMaxDynamicSharedMemorySize, SMEM_B);
        attr_set = true;
    }

    setup_kernel<<<CONV_BLOCKS + 513, 256>>>(features, W_init, b_init, W_final, b_final);
    gather_kernel<<<B_PAD / 8, 256>>>(nodes, neigh_idx, neigh_w, features, B);
    gemm_kernel<<<(B_PAD / 128) * 2, 256, SMEM_B>>>(out, B);
}

// round 13
// speedup vs baseline: 1.5586x; 1.1825x over previous
#include <cuda_runtime.h>
#include <cuda_fp16.h>
#include <cstdint>
#include <math.h>

// ---------------------------------------------------------------------------
// Shapes fixed by the dataset
#define D_DIM   256
#define E_DIM   256
#define K_NEIGH 32
#define N_NODES 200000
#define B_PAD   50048          // 391 * 128  (GEMM M-tile padded)

// Scratch (__device__ globals: no allocations allowed)
__device__ __half g_X [(size_t)B_PAD * 512];    // activation (fp16, single plane)
__device__ __half g_Wt[256 * 512];              // W^T single plane (fp16) [e][k]
__device__ float  g_bc[256];                    // fused bias
__device__ __half g_F16[(size_t)N_NODES * 256]; // fp16 feature table (neigh path)

// ---------------------------------------------------------------------------
// Setup kernel (R9-proven convert shape): merged fp32->fp16 feature convert
// + fused-weight prep. blocks [0,50000): convert; [50000,50513): prep.
// ---------------------------------------------------------------------------
#define CONV_BLOCKS 50000      // 200000*256/4 float4 / 256 thr

__global__ void __launch_bounds__(256) setup_kernel(const float* __restrict__ features,
                                                    const float* __restrict__ W_init,
                                                    const float* __restrict__ b_init,
                                                    const float* __restrict__ W_final,
                                                    const float* __restrict__ b_final) {
    if (blockIdx.x < CONV_BLOCKS) {
        const size_t i = (size_t)blockIdx.x * 256 + threadIdx.x;   // one float4 each
        float4 v = ((const float4*)features)[i];
        __half2 p0 = __floats2half2_rn(v.x, v.y);
        __half2 p1 = __floats2half2_rn(v.z, v.w);
        uint2 u;
        u.x = *(uint32_t*)&p0;
        u.y = *(uint32_t*)&p1;
        *(uint2*)(g_F16 + i * 4) = u;
        return;
    }

    __shared__ float sh[256];
    const int d = blockIdx.x - CONV_BLOCKS;
    const int e = threadIdx.x;

    if (d < 256) {
        sh[e] = W_init[d * 256 + e];
        __syncthreads();
        float s0 = 0.f, s1 = 0.f, s2 = 0.f, s3 = 0.f;
#pragma unroll 8
        for (int j = 0; j < 256; j += 4) {
            s0 += sh[j + 0] * W_final[(j + 0) * 256 + e];
            s1 += sh[j + 1] * W_final[(j + 1) * 256 + e];
            s2 += sh[j + 2] * W_final[(j + 2) * 256 + e];
            s3 += sh[j + 3] * W_final[(j + 3) * 256 + e];
        }
        g_Wt[e * 512 + d] = __float2half_rn((s0 + s1) + (s2 + s3));
    } else if (d < 512) {
        g_Wt[e * 512 + d] = __float2half_rn(W_final[d * 256 + e]);
    } else {
        sh[e] = b_init[e];
        __syncthreads();
        float s0 = 0.f, s1 = 0.f, s2 = 0.f, s3 = 0.f;
#pragma unroll 8
        for (int j = 0; j < 256; j += 4) {
            s0 += sh[j + 0] * W_final[(j + 0) * 256 + e];
            s1 += sh[j + 1] * W_final[(j + 1) * 256 + e];
            s2 += sh[j + 2] * W_final[(j + 2) * 256 + e];
            s3 += sh[j + 3] * W_final[(j + 3) * 256 + e];
        }
        g_bc[e] = b_final[e] + (s0 + s1) + (s2 + s3);
    }
}

// ---------------------------------------------------------------------------
// Kernel 1: gather + weighted-mean aggregate -> X fp16 (single plane).
// Self path: fp32 rows -> fp16. Neighbor path: fp16 table.
// ---------------------------------------------------------------------------
static __device__ __forceinline__ void store4_h(float4 v, __half* p) {
    __half2 H0 = __floats2half2_rn(v.x, v.y);
    __half2 H1 = __floats2half2_rn(v.z, v.w);
    uint2 u;
    u.x = *(uint32_t*)&H0; u.y = *(uint32_t*)&H1;
    *(uint2*)p = u;
}

__global__ void __launch_bounds__(256) gather_kernel(const int*   __restrict__ nodes,
                                                     const int*   __restrict__ neigh_idx,
                                                     const float* __restrict__ neigh_w,
                                                     const float* __restrict__ features,
                                                     int B) {
    const int wid  = threadIdx.x >> 5;
    const int lane = threadIdx.x & 31;
    const int b    = blockIdx.x * 8 + wid;
    if (b >= B_PAD) return;

    __half* x = g_X + (size_t)b * 512;

    float4 s0, s1, a0, a1;
    if (b < B) {
        const int node = nodes[b];
        const float4* fs = (const float4*)(features + (size_t)node * D_DIM);
        s0 = fs[lane];
        s1 = fs[lane + 32];

        const float w_mine   = neigh_w[b * K_NEIGH + lane];
        const int   idx_mine = neigh_idx[b * K_NEIGH + lane];
        float ws = w_mine;
#pragma unroll
        for (int o = 16; o > 0; o >>= 1)
            ws += __shfl_xor_sync(0xffffffffu, ws, o);
        const float inv = 1.0f / ws;

        a0 = make_float4(0.f, 0.f, 0.f, 0.f);
        a1 = make_float4(0.f, 0.f, 0.f, 0.f);
#pragma unroll 8
        for (int k = 0; k < K_NEIGH; k++) {
            const float wk = __shfl_sync(0xffffffffu, w_mine, k) * inv;
            const int   ik = __shfl_sync(0xffffffffu, idx_mine, k);
            uint4 v = *(const uint4*)(g_F16 + (size_t)ik * 256 + lane * 8);
            float2 f0 = __half22float2(*(__half2*)&v.x);
            float2 f1 = __half22float2(*(__half2*)&v.y);
            float2 f2 = __half22float2(*(__half2*)&v.z);
            float2 f3 = __half22float2(*(__half2*)&v.w);
            a0.x += wk * f0.x; a0.y += wk * f0.y; a0.z += wk * f1.x; a0.w += wk * f1.y;
            a1.x += wk * f2.x; a1.y += wk * f2.y; a1.z += wk * f3.x; a1.w += wk * f3.y;
        }
    } else {
        s0 = s1 = a0 = a1 = make_float4(0.f, 0.f, 0.f, 0.f);
    }

    store4_h(s0, x + lane * 4);
    store4_h(s1, x + 128 + lane * 4);
    store4_h(a0, x + 256 + lane * 8);
    store4_h(a1, x + 256 + lane * 8 + 4);
}

// ---------------------------------------------------------------------------
// Kernel 2: tensor-core GEMM via mma.sync (f16 x f16 -> f32), cp.async
// double-buffered. z = A * W, single MMA product.
// CTA tile 128M x 128N, 8 warps (4M x 2N), warp tile 32x64.
// KC=32 per stage, 16 stages, 2 smem buffers (20KB each), 2 CTAs/SM.
// ---------------------------------------------------------------------------
#define KC       32
#define KSTRIDE  40                  // padded row stride (fp16 elems) — conflict-free
#define PLANE_E  (128 * KSTRIDE)     // 5120 elems per plane
#define STAGE_E  (2 * PLANE_E)       // 10240 elems per stage (A, W)
#define STAGE_B  (STAGE_E * 2)       // 20480 bytes
#define SMEM_B   (2 * STAGE_B)       // 40960 bytes

#define OFF_A    0
#define OFF_W    PLANE_E

static __device__ __forceinline__ uint32_t smem_u32(const void* p) {
    uint32_t a;
    asm("{ .reg .u64 t; cvta.to.shared.u64 t, %1; cvt.u32.u64 %0, t; }" : "=r"(a) : "l"(p));
    return a;
}
static __device__ __forceinline__ void cp16(uint32_t saddr, const void* g) {
    asm volatile("cp.async.cg.shared.global [%0], [%1], 16;"
                 :: "r"(saddr), "l"((size_t)__cvta_generic_to_global(g)));
}
#define CP_COMMIT() asm volatile("cp.async.commit_group;" ::: "memory")
#define CP_WAIT(n)  asm volatile("cp.async.wait_group %0;" :: "n"(n) : "memory")

static __device__ __forceinline__ void mma16816(float* c, const uint32_t* a, const uint32_t* b) {
    asm volatile(
        "mma.sync.aligned.m16n8k16.row.col.f32.f16.f16.f32 "
        "{%0,%1,%2,%3}, {%4,%5,%6,%7}, {%8,%9}, {%0,%1,%2,%3};"
        : "+f"(c[0]), "+f"(c[1]), "+f"(c[2]), "+f"(c[3])
        : "r"(a[0]), "r"(a[1]), "r"(a[2]), "r"(a[3]), "r"(b[0]), "r"(b[1]));
}

__global__ void __launch_bounds__(256, 2) gemm_kernel(float* __restrict__ out, int B) {
    extern __shared__ __half smem[];
    const uint32_t sbase = smem_u32(smem);

    const int tid  = threadIdx.x;
    const int wid  = tid >> 5;
    const int lane = tid & 31;
    const int b0   = (blockIdx.x >> 1) * 128;
    const int n0   = (blockIdx.x & 1) * 128;

    const int wm = (wid & 3) * 32;    // warp M offset
    const int wn = (wid >> 2) * 64;   // warp N offset
    const int qr = lane >> 2;         // 0..7
    const int qc = lane & 3;          // 0..3

    const int row0 = tid >> 2,          seg0 = tid & 3;          // rows 0..63
    const int row1 = (tid + 256) >> 2,  seg1 = tid & 3;          // rows 64..127

    float acc[2][8][4];
#pragma unroll
    for (int mi = 0; mi < 2; mi++)
#pragma unroll
        for (int ni = 0; ni < 8; ni++)
#pragma unroll
            for (int j = 0; j < 4; j++)
                acc[mi][ni][j] = 0.f;

    auto prefetch = [&](int buf, int kc) {
        const uint32_t sb = sbase + (uint32_t)buf * STAGE_B;
        {
            const size_t goA = (size_t)(b0 + row0) * 512 + kc + seg0 * 8;
            const size_t goW = (size_t)(n0 + row0) * 512 + kc + seg0 * 8;
            const uint32_t so = (uint32_t)(row0 * KSTRIDE + seg0 * 8) * 2;
            cp16(sb + OFF_A * 2 + so, g_X  + goA);
            cp16(sb + OFF_W * 2 + so, g_Wt + goW);
        }
        {
            const size_t goA = (size_t)(b0 + row1) * 512 + kc + seg1 * 8;
            const size_t goW = (size_t)(n0 + row1) * 512 + kc + seg1 * 8;
            const uint32_t so = (uint32_t)(row1 * KSTRIDE + seg1 * 8) * 2;
            cp16(sb + OFF_A * 2 + so, g_X  + goA);
            cp16(sb + OFF_W * 2 + so, g_Wt + goW);
        }
    };

    prefetch(0, 0);
    CP_COMMIT();

    for (int chunk = 0; chunk < 16; chunk++) {
        if (chunk + 1 < 16) {
            prefetch((chunk + 1) & 1, (chunk + 1) * KC);
            CP_COMMIT();
            CP_WAIT(1);          // current buffer's loads complete
        } else {
            CP_WAIT(0);
        }
        __syncthreads();

        const __half* st = smem + (chunk & 1) * STAGE_E;
        const __half* sA = st + OFF_A;
        const __half* sW = st + OFF_W;

#pragma unroll
        for (int kk = 0; kk < KC; kk += 16) {
            uint32_t a[2][4];
#pragma unroll
            for (int mi = 0; mi < 2; mi++) {
                const int r0 = wm + mi * 16 + qr;
                const int c0 = kk + qc * 2;
                a[mi][0] = *(const uint32_t*)(sA + (r0)     * KSTRIDE + c0);
                a[mi][1] = *(const uint32_t*)(sA + (r0 + 8) * KSTRIDE + c0);
                a[mi][2] = *(const uint32_t*)(sA + (r0)     * KSTRIDE + c0 + 8);
                a[mi][3] = *(const uint32_t*)(sA + (r0 + 8) * KSTRIDE + c0 + 8);
            }
#pragma unroll
            for (int ni = 0; ni < 8; ni++) {
                const int n  = wn + ni * 8 + qr;
                const int k0 = kk + qc * 2;
                uint32_t bw[2];
                bw[0] = *(const uint32_t*)(sW + n * KSTRIDE + k0);
                bw[1] = *(const uint32_t*)(sW + n * KSTRIDE + k0 + 8);
#pragma unroll
                for (int mi = 0; mi < 2; mi++)
                    mma16816(acc[mi][ni], a[mi], bw);
            }
        }
        __syncthreads();   // buffer consumed; next iteration may overwrite it
    }

    // ---- epilogue: bias + swish + store ----
#pragma unroll
    for (int mi = 0; mi < 2; mi++) {
        const int row = b0 + wm + mi * 16 + qr;
#pragma unroll
        for (int ni = 0; ni < 8; ni++) {
            const int col = n0 + wn + ni * 8 + qc * 2;
            const float b_0 = g_bc[col], b_1 = g_bc[col + 1];

            if (row < B) {
                float z0 = acc[mi][ni][0] + b_0;
                float z1 = acc[mi][ni][1] + b_1;
                float2 o;
                o.x = z0 / (1.f + expf(-z0));
                o.y = z1 / (1.f + expf(-z1));
                *(float2*)(out + (size_t)row * E_DIM + col) = o;
            }
            if (row + 8 < B) {
                float z2 = acc[mi][ni][2] + b_0;
                float z3 = acc[mi][ni][3] + b_1;
                float2 o;
                o.x = z2 / (1.f + expf(-z2));
                o.y = z3 / (1.f + expf(-z3));
                *(float2*)(out + (size_t)(row + 8) * E_DIM + col) = o;
            }
        }
    }
}

// ---------------------------------------------------------------------------
extern "C" void kernel_launch(void* const* d_in, const int* in_sizes, int n_in,
                              void* d_out, int out_size) {
    const int*   nodes     = (const int*)  d_in[0];
    const int*   neigh_idx = (const int*)  d_in[1];
    const float* neigh_w   = (const float*)d_in[2];
    const float* features  = (const float*)d_in[3];
    const float* W_init    = (const float*)d_in[4];
    const float* b_init    = (const float*)d_in[5];
    const float* W_final   = (const float*)d_in[6];
    const float* b_final   = (const float*)d_in[7];
    float*       out       = (float*)d_out;

    const int B = in_sizes[0];

    static bool attr_set = false;
    if (!attr_set) {
        cudaFuncSetAttribute(gemm_kernel, cudaFuncAttributeMaxDynamicSharedMemorySize, SMEM_B);
        attr_set = true;
    }

    setup_kernel<<<CONV_BLOCKS + 513, 256>>>(features, W_init, b_init, W_final, b_final);
    gather_kernel<<<B_PAD / 8, 256>>>(nodes, neigh_idx, neigh_w, features, B);
    gemm_kernel<<<(B_PAD / 128) * 2, 256, SMEM_B>>>(out, B);
}

// round 14
// speedup vs baseline: 1.5643x; 1.0037x over previous
#include <cuda_runtime.h>
#include <cuda_fp16.h>
#include <cstdint>
#include <math.h>

// ---------------------------------------------------------------------------
// Shapes fixed by the dataset
#define D_DIM   256
#define E_DIM   256
#define K_NEIGH 32
#define N_NODES 200000
#define B_PAD   50048          // 782 * 64  (GEMM M-tile padded)

// Scratch (__device__ globals: no allocations allowed)
__device__ __half g_X [(size_t)B_PAD * 512];    // activation (fp16, single plane)
__device__ __half g_Wt[256 * 512];              // W^T single plane (fp16) [e][k]
__device__ float  g_bc[256];                    // fused bias
__device__ __half g_F16[(size_t)N_NODES * 256]; // fp16 feature table (neigh path)

// ---------------------------------------------------------------------------
// Setup kernel: merged fp32->fp16 feature convert + fused-weight prep.
// Convert: 2 float4 per thread at COALESCED grid stride (MLP=2).
// blocks [0,25000): convert; [25000,25513): prep.
// ---------------------------------------------------------------------------
#define CONV_BLOCKS 25000
#define CONV_STRIDE ((size_t)CONV_BLOCKS * 256)     // 6.4M float4s per pass

__global__ void __launch_bounds__(256) setup_kernel(const float* __restrict__ features,
                                                    const float* __restrict__ W_init,
                                                    const float* __restrict__ b_init,
                                                    const float* __restrict__ W_final,
                                                    const float* __restrict__ b_final) {
    if (blockIdx.x < CONV_BLOCKS) {
        const size_t i0 = (size_t)blockIdx.x * 256 + threadIdx.x;
        const size_t i1 = i0 + CONV_STRIDE;
        float4 v0 = ((const float4*)features)[i0];
        float4 v1 = ((const float4*)features)[i1];
        {
            __half2 p0 = __floats2half2_rn(v0.x, v0.y);
            __half2 p1 = __floats2half2_rn(v0.z, v0.w);
            uint2 u; u.x = *(uint32_t*)&p0; u.y = *(uint32_t*)&p1;
            *(uint2*)(g_F16 + i0 * 4) = u;
        }
        {
            __half2 p0 = __floats2half2_rn(v1.x, v1.y);
            __half2 p1 = __floats2half2_rn(v1.z, v1.w);
            uint2 u; u.x = *(uint32_t*)&p0; u.y = *(uint32_t*)&p1;
            *(uint2*)(g_F16 + i1 * 4) = u;
        }
        return;
    }

    __shared__ float sh[256];
    const int d = blockIdx.x - CONV_BLOCKS;
    const int e = threadIdx.x;

    if (d < 256) {
        sh[e] = W_init[d * 256 + e];
        __syncthreads();
        float s0 = 0.f, s1 = 0.f, s2 = 0.f, s3 = 0.f;
#pragma unroll 8
        for (int j = 0; j < 256; j += 4) {
            s0 += sh[j + 0] * W_final[(j + 0) * 256 + e];
            s1 += sh[j + 1] * W_final[(j + 1) * 256 + e];
            s2 += sh[j + 2] * W_final[(j + 2) * 256 + e];
            s3 += sh[j + 3] * W_final[(j + 3) * 256 + e];
        }
        g_Wt[e * 512 + d] = __float2half_rn((s0 + s1) + (s2 + s3));
    } else if (d < 512) {
        g_Wt[e * 512 + d] = __float2half_rn(W_final[d * 256 + e]);
    } else {
        sh[e] = b_init[e];
        __syncthreads();
        float s0 = 0.f, s1 = 0.f, s2 = 0.f, s3 = 0.f;
#pragma unroll 8
        for (int j = 0; j < 256; j += 4) {
            s0 += sh[j + 0] * W_final[(j + 0) * 256 + e];
            s1 += sh[j + 1] * W_final[(j + 1) * 256 + e];
            s2 += sh[j + 2] * W_final[(j + 2) * 256 + e];
            s3 += sh[j + 3] * W_final[(j + 3) * 256 + e];
        }
        g_bc[e] = b_final[e] + (s0 + s1) + (s2 + s3);
    }
}

// ---------------------------------------------------------------------------
// Kernel 1 (unchanged, proven): gather + weighted-mean -> X fp16 single plane.
// ---------------------------------------------------------------------------
static __device__ __forceinline__ void store4_h(float4 v, __half* p) {
    __half2 H0 = __floats2half2_rn(v.x, v.y);
    __half2 H1 = __floats2half2_rn(v.z, v.w);
    uint2 u;
    u.x = *(uint32_t*)&H0; u.y = *(uint32_t*)&H1;
    *(uint2*)p = u;
}

__global__ void __launch_bounds__(256) gather_kernel(const int*   __restrict__ nodes,
                                                     const int*   __restrict__ neigh_idx,
                                                     const float* __restrict__ neigh_w,
                                                     const float* __restrict__ features,
                                                     int B) {
    const int wid  = threadIdx.x >> 5;
    const int lane = threadIdx.x & 31;
    const int b    = blockIdx.x * 8 + wid;
    if (b >= B_PAD) return;

    __half* x = g_X + (size_t)b * 512;

    float4 s0, s1, a0, a1;
    if (b < B) {
        const int node = nodes[b];
        const float4* fs = (const float4*)(features + (size_t)node * D_DIM);
        s0 = fs[lane];
        s1 = fs[lane + 32];

        const float w_mine   = neigh_w[b * K_NEIGH + lane];
        const int   idx_mine = neigh_idx[b * K_NEIGH + lane];
        float ws = w_mine;
#pragma unroll
        for (int o = 16; o > 0; o >>= 1)
            ws += __shfl_xor_sync(0xffffffffu, ws, o);
        const float inv = 1.0f / ws;

        a0 = make_float4(0.f, 0.f, 0.f, 0.f);
        a1 = make_float4(0.f, 0.f, 0.f, 0.f);
#pragma unroll 8
        for (int k = 0; k < K_NEIGH; k++) {
            const float wk = __shfl_sync(0xffffffffu, w_mine, k) * inv;
            const int   ik = __shfl_sync(0xffffffffu, idx_mine, k);
            uint4 v = *(const uint4*)(g_F16 + (size_t)ik * 256 + lane * 8);
            float2 f0 = __half22float2(*(__half2*)&v.x);
            float2 f1 = __half22float2(*(__half2*)&v.y);
            float2 f2 = __half22float2(*(__half2*)&v.z);
            float2 f3 = __half22float2(*(__half2*)&v.w);
            a0.x += wk * f0.x; a0.y += wk * f0.y; a0.z += wk * f1.x; a0.w += wk * f1.y;
            a1.x += wk * f2.x; a1.y += wk * f2.y; a1.z += wk * f3.x; a1.w += wk * f3.y;
        }
    } else {
        s0 = s1 = a0 = a1 = make_float4(0.f, 0.f, 0.f, 0.f);
    }

    store4_h(s0, x + lane * 4);
    store4_h(s1, x + 128 + lane * 4);
    store4_h(a0, x + 256 + lane * 8);
    store4_h(a1, x + 256 + lane * 8 + 4);
}

// ---------------------------------------------------------------------------
// Kernel 2: tensor-core GEMM, CTA tile 64M x 256N (X read ONCE), 256 threads,
// 8 warps (2M x 4N), warp tile 32x64. KC=32 double-buffered cp.async.
// smem: A 64xKC + W 256xKC per stage, 25.6KB/stage, 51.2KB total, 2 CTAs/SM.
// ---------------------------------------------------------------------------
#define KC        32
#define KSTRIDE   40                 // padded row stride (fp16 elems) — conflict-free
#define A_PLANE_E (64 * KSTRIDE)     // 2560
#define W_PLANE_E (256 * KSTRIDE)    // 10240
#define STAGE_E   (A_PLANE_E + W_PLANE_E)  // 12800 elems
#define STAGE_B   (STAGE_E * 2)      // 25600 bytes
#define SMEM_B    (2 * STAGE_B)      // 51200 bytes

#define OFF_A     0
#define OFF_W     A_PLANE_E

static __device__ __forceinline__ uint32_t smem_u32(const void* p) {
    uint32_t a;
    asm("{ .reg .u64 t; cvta.to.shared.u64 t, %1; cvt.u32.u64 %0, t; }" : "=r"(a) : "l"(p));
    return a;
}
static __device__ __forceinline__ void cp16(uint32_t saddr, const void* g) {
    asm volatile("cp.async.cg.shared.global [%0], [%1], 16;"
                 :: "r"(saddr), "l"((size_t)__cvta_generic_to_global(g)));
}
#define CP_COMMIT() asm volatile("cp.async.commit_group;" ::: "memory")
#define CP_WAIT(n)  asm volatile("cp.async.wait_group %0;" :: "n"(n) : "memory")

static __device__ __forceinline__ void mma16816(float* c, const uint32_t* a, const uint32_t* b) {
    asm volatile(
        "mma.sync.aligned.m16n8k16.row.col.f32.f16.f16.f32 "
        "{%0,%1,%2,%3}, {%4,%5,%6,%7}, {%8,%9}, {%0,%1,%2,%3};"
        : "+f"(c[0]), "+f"(c[1]), "+f"(c[2]), "+f"(c[3])
        : "r"(a[0]), "r"(a[1]), "r"(a[2]), "r"(a[3]), "r"(b[0]), "r"(b[1]));
}

__global__ void __launch_bounds__(256, 2) gemm_kernel(float* __restrict__ out, int B) {
    extern __shared__ __half smem[];
    const uint32_t sbase = smem_u32(smem);

    const int tid  = threadIdx.x;
    const int wid  = tid >> 5;
    const int lane = tid & 31;
    const int b0   = blockIdx.x * 64;

    const int wm = (wid & 1) * 32;    // warp M offset (2 M-slots over 64)
    const int wn = (wid >> 1) * 64;   // warp N offset (4 N-slots over 256)
    const int qr = lane >> 2;         // 0..7
    const int qc = lane & 3;          // 0..3

    // staging: A = 256 16B-chunks (j=0), W = 1024 chunks (j=1..4)
    const int rowA = tid >> 2, segA = tid & 3;

    float acc[2][8][4];
#pragma unroll
    for (int mi = 0; mi < 2; mi++)
#pragma unroll
        for (int ni = 0; ni < 8; ni++)
#pragma unroll
            for (int j = 0; j < 4; j++)
                acc[mi][ni][j] = 0.f;

    auto prefetch = [&](int buf, int kc) {
        const uint32_t sb = sbase + (uint32_t)buf * STAGE_B;
        // A: 64 rows x 4 segs = 256 chunks
        {
            const size_t go = (size_t)(b0 + rowA) * 512 + kc + segA * 8;
            const uint32_t so = (uint32_t)(rowA * KSTRIDE + segA * 8) * 2;
            cp16(sb + OFF_A * 2 + so, g_X + go);
        }
        // W: 256 rows x 4 segs = 1024 chunks, 4 per thread
#pragma unroll
        for (int j = 0; j < 4; j++) {
            const int w   = tid + j * 256;
            const int row = w >> 2, seg = w & 3;
            const size_t go = (size_t)row * 512 + kc + seg * 8;
            const uint32_t so = (uint32_t)(row * KSTRIDE + seg * 8) * 2;
            cp16(sb + OFF_W * 2 + so, g_Wt + go);
        }
    };

    prefetch(0, 0);
    CP_COMMIT();

    for (int chunk = 0; chunk < 16; chunk++) {
        if (chunk + 1 < 16) {
            prefetch((chunk + 1) & 1, (chunk + 1) * KC);
            CP_COMMIT();
            CP_WAIT(1);          // current buffer's loads complete
        } else {
            CP_WAIT(0);
        }
        __syncthreads();

        const __half* st = smem + (chunk & 1) * STAGE_E;
        const __half* sA = st + OFF_A;
        const __half* sW = st + OFF_W;

#pragma unroll
        for (int kk = 0; kk < KC; kk += 16) {
            uint32_t a[2][4];
#pragma unroll
            for (int mi = 0; mi < 2; mi++) {
                const int r0 = wm + mi * 16 + qr;
                const int c0 = kk + qc * 2;
                a[mi][0] = *(const uint32_t*)(sA + (r0)     * KSTRIDE + c0);
                a[mi][1] = *(const uint32_t*)(sA + (r0 + 8) * KSTRIDE + c0);
                a[mi][2] = *(const uint32_t*)(sA + (r0)     * KSTRIDE + c0 + 8);
                a[mi][3] = *(const uint32_t*)(sA + (r0 + 8) * KSTRIDE + c0 + 8);
            }
#pragma unroll
            for (int ni = 0; ni < 8; ni++) {
                const int n  = wn + ni * 8 + qr;
                const int k0 = kk + qc * 2;
                uint32_t bw[2];
                bw[0] = *(const uint32_t*)(sW + n * KSTRIDE + k0);
                bw[1] = *(const uint32_t*)(sW + n * KSTRIDE + k0 + 8);
#pragma unroll
                for (int mi = 0; mi < 2; mi++)
                    mma16816(acc[mi][ni], a[mi], bw);
            }
        }
        __syncthreads();   // buffer consumed; next iteration may overwrite it
    }

    // ---- epilogue: bias + swish + store ----
#pragma unroll
    for (int mi = 0; mi < 2; mi++) {
        const int row = b0 + wm + mi * 16 + qr;
#pragma unroll
        for (int ni = 0; ni < 8; ni++) {
            const int col = wn + ni * 8 + qc * 2;
            const float b_0 = g_bc[col], b_1 = g_bc[col + 1];

            if (row < B) {
                float z0 = acc[mi][ni][0] + b_0;
                float z1 = acc[mi][ni][1] + b_1;
                float2 o;
                o.x = z0 / (1.f + expf(-z0));
                o.y = z1 / (1.f + expf(-z1));
                *(float2*)(out + (size_t)row * E_DIM + col) = o;
            }
            if (row + 8 < B) {
                float z2 = acc[mi][ni][2] + b_0;
                float z3 = acc[mi][ni][3] + b_1;
                float2 o;
                o.x = z2 / (1.f + expf(-z2));
                o.y = z3 / (1.f + expf(-z3));
                *(float2*)(out + (size_t)(row + 8) * E_DIM + col) = o;
            }
        }
    }
}

// ---------------------------------------------------------------------------
extern "C" void kernel_launch(void* const* d_in, const int* in_sizes, int n_in,
                              void* d_out, int out_size) {
    const int*   nodes     = (const int*)  d_in[0];
    const int*   neigh_idx = (const int*)  d_in[1];
    const float* neigh_w   = (const float*)d_in[2];
    const float* features  = (const float*)d_in[3];
    const float* W_init    = (const float*)d_in[4];
    const float* b_init    = (const float*)d_in[5];
    const float* W_final   = (const float*)d_in[6];
    const float* b_final   = (const float*)d_in[7];
    float*       out       = (float*)d_out;

    const int B = in_sizes[0];

    static bool attr_set = false;
    if (!attr_set) {
        cudaFuncSetAttribute(gemm_kernel, cudaFuncAttributeMaxDynamicSharedMemorySize, SMEM_B);
        attr_set = true;
    }

    setup_kernel<<<CONV_BLOCKS + 513, 256>>>(features, W_init, b_init, W_final, b_final);
    gather_kernel<<<B_PAD / 8, 256>>>(nodes, neigh_idx, neigh_w, features, B);
    gemm_kernel<<<B_PAD / 64, 256, SMEM_B>>>(out, B);
}